// round 6
// baseline (speedup 1.0000x reference)
#include <cuda_runtime.h>
#include <cuda_bf16.h>
#include <cuda_fp16.h>
#include <cuda_fp8.h>
#include <math_constants.h>
#include <cstdint>

#define BATCH  2
#define SEQ    2048
#define DMODEL 1024
#define NHEAD  16
#define HDIM   64
#define MTOT   4096
#define NELX   (MTOT*DMODEL)
#define NELW   (DMODEL*DMODEL)

// ---------------- scratch ----------------------------------------------------
__device__ __align__(16) __half  g_X16[3][NELX];
__device__ __align__(16) uint8_t g_X8h[3][NELX];
__device__ __align__(16) uint8_t g_X8l[3][NELX];
__device__ __align__(16) __half  g_W16[4][NELW];
__device__ __align__(16) uint8_t g_W8h[4][NELW];
__device__ __align__(16) uint8_t g_W8l[4][NELW];
__device__ __align__(16) __nv_bfloat16 g_QKVhi[3][BATCH*NHEAD*SEQ*HDIM];
__device__ __align__(16) __nv_bfloat16 g_QKVlo[3][BATCH*NHEAD*SEQ*HDIM];
__device__ __align__(16) __half  g_O16[NELX];
__device__ __align__(16) uint8_t g_O8h[NELX];
__device__ __align__(16) uint8_t g_O8l[NELX];

// ---------------- helpers ----------------------------------------------------
__device__ __forceinline__ uint32_t smem_u32(const void* p) {
    uint32_t a;
    asm("{ .reg .u64 t; cvta.to.shared.u64 t, %1; cvt.u32.u64 %0, t; }" : "=r"(a) : "l"(p));
    return a;
}
__device__ __forceinline__ void cp_async16(uint32_t s, const void* g) {
    asm volatile("cp.async.cg.shared.global [%0], [%1], 16;" :: "r"(s), "l"(g) : "memory");
}
#define CP_COMMIT() asm volatile("cp.async.commit_group;" ::: "memory")
#define CP_WAIT(N)  asm volatile("cp.async.wait_group %0;" :: "n"(N) : "memory")
__device__ __forceinline__ void ldsm4(uint32_t (&r)[4], uint32_t a) {
    asm volatile("ldmatrix.sync.aligned.m8n8.x4.shared.b16 {%0,%1,%2,%3}, [%4];"
                 : "=r"(r[0]), "=r"(r[1]), "=r"(r[2]), "=r"(r[3]) : "r"(a));
}
__device__ __forceinline__ void ldsm4t(uint32_t (&r)[4], uint32_t a) {
    asm volatile("ldmatrix.sync.aligned.m8n8.x4.trans.shared.b16 {%0,%1,%2,%3}, [%4];"
                 : "=r"(r[0]), "=r"(r[1]), "=r"(r[2]), "=r"(r[3]) : "r"(a));
}
__device__ __forceinline__ void mma_bf16(float (&d)[4], const uint32_t (&a)[4],
                                         uint32_t b0, uint32_t b1) {
    asm volatile("mma.sync.aligned.m16n8k16.row.col.f32.bf16.bf16.f32 "
                 "{%0,%1,%2,%3}, {%4,%5,%6,%7}, {%8,%9}, {%0,%1,%2,%3};"
                 : "+f"(d[0]), "+f"(d[1]), "+f"(d[2]), "+f"(d[3])
                 : "r"(a[0]), "r"(a[1]), "r"(a[2]), "r"(a[3]), "r"(b0), "r"(b1));
}
__device__ __forceinline__ void mma_f16(float (&d)[4], const uint32_t (&a)[4],
                                        uint32_t b0, uint32_t b1) {
    asm volatile("mma.sync.aligned.m16n8k16.row.col.f32.f16.f16.f32 "
                 "{%0,%1,%2,%3}, {%4,%5,%6,%7}, {%8,%9}, {%0,%1,%2,%3};"
                 : "+f"(d[0]), "+f"(d[1]), "+f"(d[2]), "+f"(d[3])
                 : "r"(a[0]), "r"(a[1]), "r"(a[2]), "r"(a[3]), "r"(b0), "r"(b1));
}
__device__ __forceinline__ void mma_f8(float (&d)[4], const uint32_t (&a)[4],
                                       uint32_t b0, uint32_t b1) {
    asm volatile("mma.sync.aligned.m16n8k32.row.col.f32.e4m3.e4m3.f32 "
                 "{%0,%1,%2,%3}, {%4,%5,%6,%7}, {%8,%9}, {%0,%1,%2,%3};"
                 : "+f"(d[0]), "+f"(d[1]), "+f"(d[2]), "+f"(d[3])
                 : "r"(a[0]), "r"(a[1]), "r"(a[2]), "r"(a[3]), "r"(b0), "r"(b1));
}
__device__ __forceinline__ uint32_t pack_hi(float x, float y, float& lx, float& ly) {
    __nv_bfloat16 hx = __float2bfloat16(x), hy = __float2bfloat16(y);
    lx = x - __bfloat162float(hx); ly = y - __bfloat162float(hy);
    __nv_bfloat162 p(hx, hy);
    return *(uint32_t*)&p;
}
__device__ __forceinline__ uint32_t pack2(float x, float y) {
    __nv_bfloat162 p(__float2bfloat16(x), __float2bfloat16(y));
    return *(uint32_t*)&p;
}
__device__ __forceinline__ uint32_t f8b(float x) {
    return (uint32_t)__nv_cvt_float_to_fp8(x, __NV_SATFINITE, __NV_E4M3);
}

// ============================================================================
// Splits
// ============================================================================
__global__ __launch_bounds__(256)
void split_x(const float* __restrict__ q, const float* __restrict__ k,
             const float* __restrict__ v)
{
    const int z = blockIdx.y;
    const int i = blockIdx.x * 256 + threadIdx.x;     // n4 = NELX/4
    const float* x = (z == 0) ? q : (z == 1) ? k : v;
    float4 w = ((const float4*)x)[i];
    __half h0 = __float2half(w.x), h1 = __float2half(w.y);
    __half h2 = __float2half(w.z), h3 = __float2half(w.w);
    ((__half2*)g_X16[z])[i*2+0] = __half2(h0, h1);
    ((__half2*)g_X16[z])[i*2+1] = __half2(h2, h3);
    ((uint32_t*)g_X8h[z])[i] = f8b(w.x) | (f8b(w.y) << 8) | (f8b(w.z) << 16) | (f8b(w.w) << 24);
    ((uint32_t*)g_X8l[z])[i] =
        f8b((w.x - __half2float(h0)) * 2048.f) |
        (f8b((w.y - __half2float(h1)) * 2048.f) << 8) |
        (f8b((w.z - __half2float(h2)) * 2048.f) << 16) |
        (f8b((w.w - __half2float(h3)) * 2048.f) << 24);
}

__global__ __launch_bounds__(256)
void split_w(const float* __restrict__ w0, const float* __restrict__ w1,
             const float* __restrict__ w2, const float* __restrict__ w3)
{
    const int z = blockIdx.y;
    const int i = blockIdx.x * 256 + threadIdx.x;     // n4 = NELW/4
    const float* x = (z == 0) ? w0 : (z == 1) ? w1 : (z == 2) ? w2 : w3;
    float4 w = ((const float4*)x)[i];
    __half h0 = __float2half(w.x), h1 = __float2half(w.y);
    __half h2 = __float2half(w.z), h3 = __float2half(w.w);
    ((__half2*)g_W16[z])[i*2+0] = __half2(h0, h1);
    ((__half2*)g_W16[z])[i*2+1] = __half2(h2, h3);
    ((uint32_t*)g_W8h[z])[i] = f8b(w.x*32.f) | (f8b(w.y*32.f) << 8) |
                               (f8b(w.z*32.f) << 16) | (f8b(w.w*32.f) << 24);
    ((uint32_t*)g_W8l[z])[i] =
        f8b((w.x - __half2float(h0)) * 65536.f) |
        (f8b((w.y - __half2float(h1)) * 65536.f) << 8) |
        (f8b((w.z - __half2float(h2)) * 65536.f) << 16) |
        (f8b((w.w - __half2float(h3)) * 65536.f) << 24);
}

// ============================================================================
// GEMM: fp16 main + e4m3 cross terms. CTA 128x128, BK=64, 256 thr (4m x 2n).
// PHASE 0: A=g_X16[z],W=g_W16[z] -> bf16 hi/lo headed. PHASE 1: A=g_O16 -> f32.
// ============================================================================
#define S_B16 18432
#define S_F8  36864
#define STG   77824
#define GEMM_SMEM (2*STG)    // 155648

struct GB { const float* b0; const float* b1; const float* b2; float* out; };

template<int PHASE>
__global__ __launch_bounds__(256, 1)
void gemm_f8(GB gb)
{
    extern __shared__ char smem[];
    const uint32_t sb = smem_u32(smem);
    const int tid = threadIdx.x, wid = tid >> 5, lane = tid & 31;
    const int z = blockIdx.z;
    const int n0 = blockIdx.x * 128, m0 = blockIdx.y * 128;
    const int wm = (wid & 3) * 32, wn = (wid >> 2) * 64;

    const __half*  A16 = PHASE ? g_O16 : g_X16[z];
    const uint8_t* A8h = PHASE ? g_O8h : g_X8h[z];
    const uint8_t* A8l = PHASE ? g_O8l : g_X8l[z];
    const int wz = PHASE ? 3 : z;
    const __half*  B16 = g_W16[wz];
    const uint8_t* B8h = g_W8h[wz];
    const uint8_t* B8l = g_W8l[wz];
    const float* bias = PHASE ? gb.b0 : (z == 0 ? gb.b0 : z == 1 ? gb.b1 : gb.b2);

    auto issue = [&](int ch, int buf) {
        const int k0 = ch * 64;
        const uint32_t sbb = sb + buf * STG;
#pragma unroll
        for (int i = 0; i < 8; i++) {
            const int idx = tid + i * 256;
            const int mat = idx >> 10, r = (idx >> 3) & 127, c = idx & 7;
            const __half* src = mat ? B16 : A16;
            const int rb = mat ? n0 : m0;
            cp_async16(sbb + mat * S_B16 + r * 144 + c * 16,
                       src + (size_t)(rb + r) * DMODEL + k0 + c * 8);
        }
#pragma unroll
        for (int i = 0; i < 8; i++) {
            const int j = tid + i * 256;
            const int mat = j >> 9, r = (j >> 2) & 127, c = j & 3;
            const uint8_t* src = (mat == 0) ? A8h : (mat == 1) ? A8l
                               : (mat == 2) ? B8h : B8l;
            const int rb = (mat < 2) ? m0 : n0;
            cp_async16(sbb + S_F8 + mat * 10240 + r * 80 + c * 16,
                       src + (size_t)(rb + r) * DMODEL + k0 + c * 16);
        }
        CP_COMMIT();
    };

    float acc[2][8][4], ac2[2][8][4];
#pragma unroll
    for (int mt = 0; mt < 2; mt++)
#pragma unroll
        for (int nt = 0; nt < 8; nt++)
#pragma unroll
            for (int q = 0; q < 4; q++) { acc[mt][nt][q] = 0.f; ac2[mt][nt][q] = 0.f; }

    issue(0, 0);
    const int rlo = lane & 15, khalf = (lane >> 4) * 16;

    for (int ch = 0; ch < 16; ch++) {
        const int buf = ch & 1;
        if (ch < 15) { issue(ch + 1, buf ^ 1); CP_WAIT(1); }
        else CP_WAIT(0);
        __syncthreads();
        const uint32_t base = sb + buf * STG;

#pragma unroll
        for (int ks = 0; ks < 4; ks++) {
            uint32_t a16[2][4];
#pragma unroll
            for (int mt = 0; mt < 2; mt++)
                ldsm4(a16[mt], base + (wm + mt*16 + rlo) * 144 + ks*32 + khalf);
            uint32_t b16[4][4];
#pragma unroll
            for (int nb = 0; nb < 4; nb++)
                ldsm4(b16[nb], base + S_B16 + (wn + nb*16 + rlo) * 144 + ks*32 + khalf);
#pragma unroll
            for (int mt = 0; mt < 2; mt++)
#pragma unroll
                for (int nt = 0; nt < 8; nt++) {
                    const int nb = nt >> 1, sel = nt & 1;
                    mma_f16(acc[mt][nt], a16[mt], b16[nb][sel], b16[nb][2 + sel]);
                }
        }
#pragma unroll
        for (int c32 = 0; c32 < 2; c32++) {
            uint32_t ah[2][4], al[2][4];
#pragma unroll
            for (int mt = 0; mt < 2; mt++) {
                const uint32_t ar = base + S_F8 + (wm + mt*16 + rlo) * 80 + c32*32 + khalf;
                ldsm4(ah[mt], ar);
                ldsm4(al[mt], ar + 10240);
            }
            uint32_t bh[4][4], bl[4][4];
#pragma unroll
            for (int nb = 0; nb < 4; nb++) {
                const uint32_t br = base + S_F8 + 20480 + (wn + nb*16 + rlo) * 80 + c32*32 + khalf;
                ldsm4(bh[nb], br);
                ldsm4(bl[nb], br + 10240);
            }
#pragma unroll
            for (int mt = 0; mt < 2; mt++)
#pragma unroll
                for (int nt = 0; nt < 8; nt++) {
                    const int nb = nt >> 1, sel = nt & 1;
                    mma_f8(ac2[mt][nt], ah[mt], bl[nb][sel], bl[nb][2 + sel]);
                    mma_f8(ac2[mt][nt], al[mt], bh[nb][sel], bh[nb][2 + sel]);
                }
        }
        __syncthreads();
    }

    const int grp = lane >> 2, t4 = lane & 3;
    const float cI = 1.f / 65536.f;
#pragma unroll
    for (int mt = 0; mt < 2; mt++)
#pragma unroll
        for (int h2 = 0; h2 < 2; h2++) {
            const int m = m0 + wm + mt * 16 + grp + h2 * 8;
#pragma unroll
            for (int nt = 0; nt < 8; nt++) {
                const int n = n0 + wn + nt * 8 + t4 * 2;
                const float v0 = acc[mt][nt][h2*2+0] + ac2[mt][nt][h2*2+0]*cI + bias[n];
                const float v1 = acc[mt][nt][h2*2+1] + ac2[mt][nt][h2*2+1]*cI + bias[n+1];
                if (PHASE == 1) {
                    float2 v; v.x = v0; v.y = v1;
                    *(float2*)&gb.out[(size_t)m * DMODEL + n] = v;
                } else {
                    const int b = m >> 11, s = m & (SEQ-1), h = n >> 6, dk = n & (HDIM-1);
                    const size_t o = (((size_t)(b * NHEAD + h)) * SEQ + s) * HDIM + dk;
                    float l0, l1;
                    const uint32_t hp = pack_hi(v0, v1, l0, l1);
                    *(uint32_t*)&g_QKVhi[z][o] = hp;
                    *(uint32_t*)&g_QKVlo[z][o] = pack2(l0, l1);
                }
            }
        }
}

// ============================================================================
// Flash attention (bf16x3 core, unchanged from R4). Epilogue -> fp16+fp8.
// ============================================================================
#define F_QLO   (128*144)
#define F_STG   (2*128*144)
#define F_TILE  (64*144)
#define F_STAGEB (4*F_TILE)
#define FLASH_SMEM (F_STG + 2*F_STAGEB)  // 110592

__global__ __launch_bounds__(256, 1)
void flash_hmma()
{
    extern __shared__ char smem[];
    const uint32_t sb = smem_u32(smem);
    const int tid = threadIdx.x, wid = tid >> 5, lane = tid & 31;
    const int qt = (int)(gridDim.x - 1) - (int)blockIdx.x;
    const int bh = blockIdx.y;
    const int bb = bh >> 4, hd = bh & 15;
    const int wq = wid * 16;
    const int grp = lane >> 2, t4 = lane & 3;
    const int qbase = qt * 128;
    const size_t bhoff = (size_t)bh * SEQ * HDIM;
    const __nv_bfloat16 *Qhi_ = g_QKVhi[0], *Qlo_ = g_QKVlo[0];
    const __nv_bfloat16 *Khi_ = g_QKVhi[1], *Klo_ = g_QKVlo[1];
    const __nv_bfloat16 *Vhi_ = g_QKVhi[2], *Vlo_ = g_QKVlo[2];

#pragma unroll
    for (int i = 0; i < 8; i++) {
        const int idx = tid + i * 256;
        const int mat = idx >> 10, r = (idx >> 3) & 127, c = idx & 7;
        const __nv_bfloat16* src = (mat ? Qlo_ : Qhi_) + bhoff +
                                   (size_t)(qbase + r) * HDIM + c * 8;
        cp_async16(sb + mat * F_QLO + r * 144 + c * 16, src);
    }
    CP_COMMIT();

    const int njt = 2 * (qt + 1);
    auto issue_kv = [&](int jt, int buf) {
        const int k0 = jt * 64;
#pragma unroll
        for (int i = 0; i < 8; i++) {
            const int idx = tid + i * 256;
            const int mat = idx >> 9, r = (idx >> 3) & 63, c = idx & 7;
            const __nv_bfloat16* src = (mat == 0) ? Khi_ : (mat == 1) ? Klo_
                                     : (mat == 2) ? Vhi_ : Vlo_;
            cp_async16(sb + F_STG + buf * F_STAGEB + mat * F_TILE + r * 144 + c * 16,
                       src + bhoff + (size_t)(k0 + r) * HDIM + c * 8);
        }
        CP_COMMIT();
    };
    issue_kv(0, 0);
    CP_WAIT(1);
    __syncthreads();

    const int rlo = lane & 15, khalf = (lane >> 4) * 16;
    uint32_t qh[4][4], ql[4][4];
#pragma unroll
    for (int ks = 0; ks < 4; ks++) {
        const uint32_t a = sb + (wq + rlo) * 144 + ks * 32 + khalf;
        ldsm4(qh[ks], a);
        ldsm4(ql[ks], a + F_QLO);
    }

    float mr0 = -CUDART_INF_F, mr1 = -CUDART_INF_F, lr0 = 0.f, lr1 = 0.f;
    float out[8][4];
#pragma unroll
    for (int nf = 0; nf < 8; nf++)
#pragma unroll
        for (int q = 0; q < 4; q++) out[nf][q] = 0.f;
    const int r0g = qbase + wq + grp, r1g = r0g + 8;

    for (int jt = 0; jt < njt; jt++) {
        const int buf = jt & 1;
        if (jt + 1 < njt) { issue_kv(jt + 1, buf ^ 1); CP_WAIT(1); }
        else CP_WAIT(0);
        __syncthreads();
        const uint32_t kb = sb + F_STG + buf * F_STAGEB;

        float s[8][4];
#pragma unroll
        for (int nf = 0; nf < 8; nf++)
#pragma unroll
            for (int q = 0; q < 4; q++) s[nf][q] = 0.f;

#pragma unroll
        for (int ks = 0; ks < 4; ks++) {
            uint32_t kh[4][4], kl[4][4];
#pragma unroll
            for (int nb = 0; nb < 4; nb++) {
                const uint32_t a = kb + (nb * 16 + rlo) * 144 + ks * 32 + khalf;
                ldsm4(kh[nb], a);
                ldsm4(kl[nb], a + F_TILE);
            }
#pragma unroll
            for (int nf = 0; nf < 8; nf++) {
                const int nb = nf >> 1, sel = nf & 1;
                mma_bf16(s[nf], qh[ks], kh[nb][sel], kh[nb][2 + sel]);
                mma_bf16(s[nf], qh[ks], kl[nb][sel], kl[nb][2 + sel]);
                mma_bf16(s[nf], ql[ks], kh[nb][sel], kh[nb][2 + sel]);
            }
        }

        const int k0 = jt * 64;
        const bool maskt = (jt >= njt - 2);
#pragma unroll
        for (int nf = 0; nf < 8; nf++) {
#pragma unroll
            for (int q = 0; q < 4; q++) s[nf][q] *= 0.125f;
            if (maskt) {
                const int c0 = k0 + nf * 8 + t4 * 2, c1 = c0 + 1;
                if (c0 > r0g) s[nf][0] = -1e9f;
                if (c1 > r0g) s[nf][1] = -1e9f;
                if (c0 > r1g) s[nf][2] = -1e9f;
                if (c1 > r1g) s[nf][3] = -1e9f;
            }
        }

        float mx0 = -CUDART_INF_F, mx1 = -CUDART_INF_F;
#pragma unroll
        for (int nf = 0; nf < 8; nf++) {
            mx0 = fmaxf(mx0, fmaxf(s[nf][0], s[nf][1]));
            mx1 = fmaxf(mx1, fmaxf(s[nf][2], s[nf][3]));
        }
        mx0 = fmaxf(mx0, __shfl_xor_sync(0xffffffffu, mx0, 1));
        mx0 = fmaxf(mx0, __shfl_xor_sync(0xffffffffu, mx0, 2));
        mx1 = fmaxf(mx1, __shfl_xor_sync(0xffffffffu, mx1, 1));
        mx1 = fmaxf(mx1, __shfl_xor_sync(0xffffffffu, mx1, 2));
        const float mn0 = fmaxf(mr0, mx0), mn1 = fmaxf(mr1, mx1);
        const float cr0 = __expf(mr0 - mn0), cr1 = __expf(mr1 - mn1);
        float sum0 = 0.f, sum1 = 0.f;
#pragma unroll
        for (int nf = 0; nf < 8; nf++) {
            s[nf][0] = __expf(s[nf][0] - mn0); sum0 += s[nf][0];
            s[nf][1] = __expf(s[nf][1] - mn0); sum0 += s[nf][1];
            s[nf][2] = __expf(s[nf][2] - mn1); sum1 += s[nf][2];
            s[nf][3] = __expf(s[nf][3] - mn1); sum1 += s[nf][3];
        }
        sum0 += __shfl_xor_sync(0xffffffffu, sum0, 1);
        sum0 += __shfl_xor_sync(0xffffffffu, sum0, 2);
        sum1 += __shfl_xor_sync(0xffffffffu, sum1, 1);
        sum1 += __shfl_xor_sync(0xffffffffu, sum1, 2);
        lr0 = lr0 * cr0 + sum0;
        lr1 = lr1 * cr1 + sum1;
        mr0 = mn0; mr1 = mn1;
#pragma unroll
        for (int nf = 0; nf < 8; nf++) {
            out[nf][0] *= cr0; out[nf][1] *= cr0;
            out[nf][2] *= cr1; out[nf][3] *= cr1;
        }

        const int vrow = (lane & 7) + ((lane >> 4) << 3);
        const int vcol = (lane & 8);
#pragma unroll
        for (int ks = 0; ks < 4; ks++) {
            uint32_t ph[4], pl[4];
            {
                float l0, l1;
                ph[0] = pack_hi(s[2*ks][0],   s[2*ks][1],   l0, l1); pl[0] = pack2(l0, l1);
                ph[1] = pack_hi(s[2*ks][2],   s[2*ks][3],   l0, l1); pl[1] = pack2(l0, l1);
                ph[2] = pack_hi(s[2*ks+1][0], s[2*ks+1][1], l0, l1); pl[2] = pack2(l0, l1);
                ph[3] = pack_hi(s[2*ks+1][2], s[2*ks+1][3], l0, l1); pl[3] = pack2(l0, l1);
            }
#pragma unroll
            for (int nb = 0; nb < 4; nb++) {
                uint32_t vh[4], vl[4];
                const uint32_t a = kb + 2 * F_TILE + (ks * 16 + vrow) * 144 +
                                   (nb * 16 + vcol) * 2;
                ldsm4t(vh, a);
                ldsm4t(vl, a + F_TILE);
                mma_bf16(out[2*nb],   ph, vh[0], vh[2]);
                mma_bf16(out[2*nb],   ph, vl[0], vl[2]);
                mma_bf16(out[2*nb],   pl, vh[0], vh[2]);
                mma_bf16(out[2*nb+1], ph, vh[1], vh[3]);
                mma_bf16(out[2*nb+1], ph, vl[1], vl[3]);
                mma_bf16(out[2*nb+1], pl, vh[1], vh[3]);
            }
        }
        __syncthreads();
    }

    // epilogue: fp16 + e4m3 + e4m3(lo*2048), layout [B,S,D]
    const float inv0 = 1.f / lr0, inv1 = 1.f / lr1;
    const size_t bs0 = (size_t)(bb * SEQ + qbase + wq + grp) * DMODEL;
    const size_t bs1 = bs0 + 8 * DMODEL;
#pragma unroll
    for (int nf = 0; nf < 8; nf++) {
        const int col = hd * 64 + nf * 8 + t4 * 2;
#pragma unroll
        for (int h2 = 0; h2 < 2; h2++) {
            const float v0 = out[nf][h2*2+0] * (h2 ? inv1 : inv0);
            const float v1 = out[nf][h2*2+1] * (h2 ? inv1 : inv0);
            const size_t o = (h2 ? bs1 : bs0) + col;
            __half a = __float2half(v0), b = __float2half(v1);
            __half2 hp(a, b);
            *(uint32_t*)&g_O16[o] = *(uint32_t*)&hp;
            *(uint16_t*)&g_O8h[o] = (uint16_t)(f8b(v0) | (f8b(v1) << 8));
            *(uint16_t*)&g_O8l[o] = (uint16_t)(
                f8b((v0 - __half2float(a)) * 2048.f) |
                (f8b((v1 - __half2float(b)) * 2048.f) << 8));
        }
    }
}

// ============================================================================
extern "C" void kernel_launch(void* const* d_in, const int* in_sizes, int n_in,
                              void* d_out, int out_size)
{
    (void)in_sizes; (void)n_in; (void)out_size;
    const float* q  = (const float*)d_in[0];
    const float* k  = (const float*)d_in[1];
    const float* v  = (const float*)d_in[2];
    const float* Wq = (const float*)d_in[4];
    const float* bq = (const float*)d_in[5];
    const float* Wk = (const float*)d_in[6];
    const float* bk = (const float*)d_in[7];
    const float* Wv = (const float*)d_in[8];
    const float* bv = (const float*)d_in[9];
    const float* Wo = (const float*)d_in[10];
    const float* bo = (const float*)d_in[11];
    float* out = (float*)d_out;

    cudaFuncSetAttribute(gemm_f8<0>, cudaFuncAttributeMaxDynamicSharedMemorySize, GEMM_SMEM);
    cudaFuncSetAttribute(gemm_f8<1>, cudaFuncAttributeMaxDynamicSharedMemorySize, GEMM_SMEM);
    cudaFuncSetAttribute(flash_hmma, cudaFuncAttributeMaxDynamicSharedMemorySize, FLASH_SMEM);

    const dim3 tb(256);
    split_x<<<dim3(NELX/4/256, 3), tb>>>(q, k, v);
    split_w<<<dim3(NELW/4/256, 4), tb>>>(Wq, Wk, Wv, Wo);

    GB g0; g0.b0 = bq; g0.b1 = bk; g0.b2 = bv; g0.out = nullptr;
    gemm_f8<0><<<dim3(DMODEL/128, MTOT/128, 3), tb, GEMM_SMEM>>>(g0);

    flash_hmma<<<dim3(SEQ/128, BATCH*NHEAD), tb, FLASH_SMEM>>>();

    GB g1; g1.b0 = bo; g1.b1 = nullptr; g1.b2 = nullptr; g1.out = out;
    gemm_f8<1><<<dim3(DMODEL/128, MTOT/128, 1), tb, GEMM_SMEM>>>(g1);
}

// round 8
// speedup vs baseline: 1.0632x; 1.0632x over previous
#include <cuda_runtime.h>
#include <cuda_bf16.h>
#include <math_constants.h>
#include <cstdint>

#define BATCH  2
#define SEQ    2048
#define DMODEL 1024
#define NHEAD  16
#define HDIM   64
#define MTOT   4096
#define NELX   (MTOT*DMODEL)
#define NELW   (DMODEL*DMODEL)

// ---------------- scratch ----------------------------------------------------
__device__ __align__(16) __nv_bfloat16 g_Xhi[3][NELX];
__device__ __align__(16) __nv_bfloat16 g_Xlo[3][NELX];
__device__ __align__(16) __nv_bfloat16 g_Whi[4][NELW];
__device__ __align__(16) __nv_bfloat16 g_Wlo[4][NELW];
__device__ __align__(16) __nv_bfloat16 g_QKVhi[3][NELX];   // [B,H,S,DK]
__device__ __align__(16) __nv_bfloat16 g_QKVlo[3][NELX];
__device__ __align__(16) __nv_bfloat16 g_Ohi[NELX];        // [B,S,D]
__device__ __align__(16) __nv_bfloat16 g_Olo[NELX];

// ---------------- helpers ----------------------------------------------------
__device__ __forceinline__ uint32_t smem_u32(const void* p) {
    uint32_t a;
    asm("{ .reg .u64 t; cvta.to.shared.u64 t, %1; cvt.u32.u64 %0, t; }" : "=r"(a) : "l"(p));
    return a;
}
__device__ __forceinline__ void cp_async16(uint32_t s, const void* g) {
    asm volatile("cp.async.cg.shared.global [%0], [%1], 16;" :: "r"(s), "l"(g) : "memory");
}
#define CP_COMMIT() asm volatile("cp.async.commit_group;" ::: "memory")
#define CP_WAIT(N)  asm volatile("cp.async.wait_group %0;" :: "n"(N) : "memory")
__device__ __forceinline__ void ldsm4(uint32_t (&r)[4], uint32_t a) {
    asm volatile("ldmatrix.sync.aligned.m8n8.x4.shared.b16 {%0,%1,%2,%3}, [%4];"
                 : "=r"(r[0]), "=r"(r[1]), "=r"(r[2]), "=r"(r[3]) : "r"(a));
}
__device__ __forceinline__ void ldsm4t(uint32_t (&r)[4], uint32_t a) {
    asm volatile("ldmatrix.sync.aligned.m8n8.x4.trans.shared.b16 {%0,%1,%2,%3}, [%4];"
                 : "=r"(r[0]), "=r"(r[1]), "=r"(r[2]), "=r"(r[3]) : "r"(a));
}
__device__ __forceinline__ void mma_bf16(float (&d)[4], const uint32_t (&a)[4],
                                         uint32_t b0, uint32_t b1) {
    asm volatile("mma.sync.aligned.m16n8k16.row.col.f32.bf16.bf16.f32 "
                 "{%0,%1,%2,%3}, {%4,%5,%6,%7}, {%8,%9}, {%0,%1,%2,%3};"
                 : "+f"(d[0]), "+f"(d[1]), "+f"(d[2]), "+f"(d[3])
                 : "r"(a[0]), "r"(a[1]), "r"(a[2]), "r"(a[3]), "r"(b0), "r"(b1));
}
__device__ __forceinline__ uint32_t pack_hi(float x, float y, float& lx, float& ly) {
    __nv_bfloat16 hx = __float2bfloat16(x), hy = __float2bfloat16(y);
    lx = x - __bfloat162float(hx); ly = y - __bfloat162float(hy);
    __nv_bfloat162 p(hx, hy);
    return *(uint32_t*)&p;
}
__device__ __forceinline__ uint32_t pack2(float x, float y) {
    __nv_bfloat162 p(__float2bfloat16(x), __float2bfloat16(y));
    return *(uint32_t*)&p;
}

// ============================================================================
// Fused splits
// ============================================================================
__global__ __launch_bounds__(256)
void split_x(const float* __restrict__ q, const float* __restrict__ k,
             const float* __restrict__ v)
{
    const int z = blockIdx.y;
    const int i = blockIdx.x * 256 + threadIdx.x;
    const float* x = (z == 0) ? q : (z == 1) ? k : v;
    float4 w = ((const float4*)x)[i];
    __nv_bfloat16 h0 = __float2bfloat16(w.x), h1 = __float2bfloat16(w.y);
    __nv_bfloat16 h2 = __float2bfloat16(w.z), h3 = __float2bfloat16(w.w);
    ((__nv_bfloat162*)g_Xhi[z])[i*2+0] = __nv_bfloat162(h0, h1);
    ((__nv_bfloat162*)g_Xhi[z])[i*2+1] = __nv_bfloat162(h2, h3);
    ((__nv_bfloat162*)g_Xlo[z])[i*2+0] = __nv_bfloat162(
        __float2bfloat16(w.x - __bfloat162float(h0)),
        __float2bfloat16(w.y - __bfloat162float(h1)));
    ((__nv_bfloat162*)g_Xlo[z])[i*2+1] = __nv_bfloat162(
        __float2bfloat16(w.z - __bfloat162float(h2)),
        __float2bfloat16(w.w - __bfloat162float(h3)));
}

__global__ __launch_bounds__(256)
void split_w(const float* __restrict__ w0, const float* __restrict__ w1,
             const float* __restrict__ w2, const float* __restrict__ w3)
{
    const int z = blockIdx.y;
    const int i = blockIdx.x * 256 + threadIdx.x;
    const float* x = (z == 0) ? w0 : (z == 1) ? w1 : (z == 2) ? w2 : w3;
    float4 w = ((const float4*)x)[i];
    __nv_bfloat16 h0 = __float2bfloat16(w.x), h1 = __float2bfloat16(w.y);
    __nv_bfloat16 h2 = __float2bfloat16(w.z), h3 = __float2bfloat16(w.w);
    ((__nv_bfloat162*)g_Whi[z])[i*2+0] = __nv_bfloat162(h0, h1);
    ((__nv_bfloat162*)g_Whi[z])[i*2+1] = __nv_bfloat162(h2, h3);
    ((__nv_bfloat162*)g_Wlo[z])[i*2+0] = __nv_bfloat162(
        __float2bfloat16(w.x - __bfloat162float(h0)),
        __float2bfloat16(w.y - __bfloat162float(h1)));
    ((__nv_bfloat162*)g_Wlo[z])[i*2+1] = __nv_bfloat162(
        __float2bfloat16(w.z - __bfloat162float(h2)),
        __float2bfloat16(w.w - __bfloat162float(h3)));
}

// ============================================================================
// GEMM bf16x3, BK=32, 2 CTAs/SM target. CTA 128x128, 256 thr (4m x 2n warps).
// PHASE 0: A=g_Xhi/lo[z], W=g_Whi/lo[z] -> bf16 hi/lo headed [B,H,S,DK].
// PHASE 1: A=g_Ohi/lo,    W=g_Whi/lo[3] -> f32 flat out.
// ============================================================================
#define ROWB   80
#define TILEB  (128*ROWB)      // 10240
#define STAGEB (4*TILEB)       // 40960
#define GEMM_SMEM (2*STAGEB)   // 81920

struct GB { const float* b[3]; float* out; };

template<int PHASE>
__global__ __launch_bounds__(256, 2)
void gemm_bf16x3(GB gb)
{
    extern __shared__ char smem[];
    const uint32_t sb = smem_u32(smem);
    const int tid = threadIdx.x, wid = tid >> 5, lane = tid & 31;
    const int z = blockIdx.z;
    const int n0 = blockIdx.x * 128, m0 = blockIdx.y * 128;
    const int wm = (wid & 3) * 32, wn = (wid >> 2) * 64;

    const __nv_bfloat16* Ahi = PHASE ? g_Ohi : g_Xhi[z];
    const __nv_bfloat16* Alo = PHASE ? g_Olo : g_Xlo[z];
    const int wz = PHASE ? 3 : z;
    const __nv_bfloat16* Bhi = g_Whi[wz];
    const __nv_bfloat16* Blo = g_Wlo[wz];
    const float* bias = PHASE ? gb.b[0] : gb.b[z];

    auto issue = [&](int ch, int buf) {
        const int k0 = ch * 32;
        const uint32_t sbb = sb + buf * STAGEB;
#pragma unroll
        for (int i = 0; i < 8; i++) {
            const int idx = tid + i * 256;        // 0..2047
            const int mat = idx >> 9;             // 0 Ahi 1 Alo 2 Bhi 3 Blo
            const int r = (idx >> 2) & 127, c = idx & 3;
            const __nv_bfloat16* src = (mat == 0) ? Ahi : (mat == 1) ? Alo
                                     : (mat == 2) ? Bhi : Blo;
            const int rb = (mat < 2) ? m0 : n0;
            cp_async16(sbb + mat * TILEB + r * ROWB + c * 16,
                       src + (size_t)(rb + r) * DMODEL + k0 + c * 8);
        }
        CP_COMMIT();
    };

    float acc[2][8][4];
#pragma unroll
    for (int mt = 0; mt < 2; mt++)
#pragma unroll
        for (int nt = 0; nt < 8; nt++)
#pragma unroll
            for (int q = 0; q < 4; q++) acc[mt][nt][q] = 0.f;

    issue(0, 0);
    const int rlo = lane & 15, khalf = (lane >> 4) * 16;

    for (int ch = 0; ch < 32; ch++) {
        const int buf = ch & 1;
        if (ch < 31) { issue(ch + 1, buf ^ 1); CP_WAIT(1); }
        else CP_WAIT(0);
        __syncthreads();
        const uint32_t base = sb + buf * STAGEB;

#pragma unroll
        for (int ks = 0; ks < 2; ks++) {
            uint32_t ahi[2][4], alo[2][4];
#pragma unroll
            for (int mt = 0; mt < 2; mt++) {
                const uint32_t a = base + (wm + mt*16 + rlo) * ROWB + ks*32 + khalf;
                ldsm4(ahi[mt], a);
                ldsm4(alo[mt], a + TILEB);
            }
            uint32_t bhi[4][4], blo[4][4];
#pragma unroll
            for (int nb = 0; nb < 4; nb++) {
                const uint32_t a = base + 2*TILEB + (wn + nb*16 + rlo) * ROWB + ks*32 + khalf;
                ldsm4(bhi[nb], a);
                ldsm4(blo[nb], a + TILEB);
            }
#pragma unroll
            for (int mt = 0; mt < 2; mt++)
#pragma unroll
                for (int nt = 0; nt < 8; nt++) {
                    const int nb = nt >> 1, sel = nt & 1;
                    mma_bf16(acc[mt][nt], ahi[mt], bhi[nb][sel], bhi[nb][2 + sel]);
                    mma_bf16(acc[mt][nt], ahi[mt], blo[nb][sel], blo[nb][2 + sel]);
                    mma_bf16(acc[mt][nt], alo[mt], bhi[nb][sel], bhi[nb][2 + sel]);
                }
        }
        __syncthreads();
    }

    const int grp = lane >> 2, t4 = lane & 3;
#pragma unroll
    for (int mt = 0; mt < 2; mt++)
#pragma unroll
        for (int h2 = 0; h2 < 2; h2++) {
            const int m = m0 + wm + mt * 16 + grp + h2 * 8;
#pragma unroll
            for (int nt = 0; nt < 8; nt++) {
                const int n = n0 + wn + nt * 8 + t4 * 2;
                const float v0 = acc[mt][nt][h2*2+0] + bias[n];
                const float v1 = acc[mt][nt][h2*2+1] + bias[n+1];
                if (PHASE == 1) {
                    float2 v; v.x = v0; v.y = v1;
                    *(float2*)&gb.out[(size_t)m * DMODEL + n] = v;
                } else {
                    const int b = m >> 11, s = m & (SEQ-1), h = n >> 6, dk = n & (HDIM-1);
                    const size_t o = (((size_t)(b * NHEAD + h)) * SEQ + s) * HDIM + dk;
                    float l0, l1;
                    const uint32_t hp = pack_hi(v0, v1, l0, l1);
                    *(uint32_t*)&g_QKVhi[z][o] = hp;
                    *(uint32_t*)&g_QKVlo[z][o] = pack2(l0, l1);
                }
            }
        }
}

// ============================================================================
// Flash attention bf16x3; Q re-ldsm'd from smem (reg relief); 2 CTAs/SM target
// ============================================================================
#define F_QLO   (128*144)
#define F_STG   (2*128*144)
#define F_TILE  (64*144)
#define F_STAGEB (4*F_TILE)
#define FLASH_SMEM (F_STG + 2*F_STAGEB)  // 110592

__global__ __launch_bounds__(256, 2)
void flash_hmma()
{
    extern __shared__ char smem[];
    const uint32_t sb = smem_u32(smem);
    const int tid = threadIdx.x, wid = tid >> 5, lane = tid & 31;
    const int qt = (int)(gridDim.x - 1) - (int)blockIdx.x;
    const int bh = blockIdx.y;
    const int bb = bh >> 4, hd = bh & 15;
    const int wq = wid * 16;
    const int grp = lane >> 2, t4 = lane & 3;
    const int qbase = qt * 128;
    const size_t bhoff = (size_t)bh * SEQ * HDIM;
    const __nv_bfloat16 *Qhi_ = g_QKVhi[0], *Qlo_ = g_QKVlo[0];
    const __nv_bfloat16 *Khi_ = g_QKVhi[1], *Klo_ = g_QKVlo[1];
    const __nv_bfloat16 *Vhi_ = g_QKVhi[2], *Vlo_ = g_QKVlo[2];

#pragma unroll
    for (int i = 0; i < 8; i++) {
        const int idx = tid + i * 256;
        const int mat = idx >> 10, r = (idx >> 3) & 127, c = idx & 7;
        const __nv_bfloat16* src = (mat ? Qlo_ : Qhi_) + bhoff +
                                   (size_t)(qbase + r) * HDIM + c * 8;
        cp_async16(sb + mat * F_QLO + r * 144 + c * 16, src);
    }
    CP_COMMIT();

    const int njt = 2 * (qt + 1);
    auto issue_kv = [&](int jt, int buf) {
        const int k0 = jt * 64;
#pragma unroll
        for (int i = 0; i < 8; i++) {
            const int idx = tid + i * 256;
            const int mat = idx >> 9, r = (idx >> 3) & 63, c = idx & 7;
            const __nv_bfloat16* src = (mat == 0) ? Khi_ : (mat == 1) ? Klo_
                                     : (mat == 2) ? Vhi_ : Vlo_;
            cp_async16(sb + F_STG + buf * F_STAGEB + mat * F_TILE + r * 144 + c * 16,
                       src + bhoff + (size_t)(k0 + r) * HDIM + c * 8);
        }
        CP_COMMIT();
    };
    issue_kv(0, 0);
    CP_WAIT(1);
    __syncthreads();

    const int rlo = lane & 15, khalf = (lane >> 4) * 16;

    float mr0 = -CUDART_INF_F, mr1 = -CUDART_INF_F, lr0 = 0.f, lr1 = 0.f;
    float out[8][4];
#pragma unroll
    for (int nf = 0; nf < 8; nf++)
#pragma unroll
        for (int q = 0; q < 4; q++) out[nf][q] = 0.f;
    const int r0g = qbase + wq + grp, r1g = r0g + 8;

    for (int jt = 0; jt < njt; jt++) {
        const int buf = jt & 1;
        if (jt + 1 < njt) { issue_kv(jt + 1, buf ^ 1); CP_WAIT(1); }
        else CP_WAIT(0);
        __syncthreads();
        const uint32_t kb = sb + F_STG + buf * F_STAGEB;

        float s[8][4];
#pragma unroll
        for (int nf = 0; nf < 8; nf++)
#pragma unroll
            for (int q = 0; q < 4; q++) s[nf][q] = 0.f;

#pragma unroll
        for (int ks = 0; ks < 4; ks++) {
            uint32_t qh[4], ql[4];
            const uint32_t qa = sb + (wq + rlo) * 144 + ks * 32 + khalf;
            ldsm4(qh, qa);
            ldsm4(ql, qa + F_QLO);
            uint32_t kh[4][4], kl[4][4];
#pragma unroll
            for (int nb = 0; nb < 4; nb++) {
                const uint32_t a = kb + (nb * 16 + rlo) * 144 + ks * 32 + khalf;
                ldsm4(kh[nb], a);
                ldsm4(kl[nb], a + F_TILE);
            }
#pragma unroll
            for (int nf = 0; nf < 8; nf++) {
                const int nb = nf >> 1, sel = nf & 1;
                mma_bf16(s[nf], qh, kh[nb][sel], kh[nb][2 + sel]);
                mma_bf16(s[nf], qh, kl[nb][sel], kl[nb][2 + sel]);
                mma_bf16(s[nf], ql, kh[nb][sel], kh[nb][2 + sel]);
            }
        }

        const int k0 = jt * 64;
        const bool maskt = (jt >= njt - 2);
#pragma unroll
        for (int nf = 0; nf < 8; nf++) {
#pragma unroll
            for (int q = 0; q < 4; q++) s[nf][q] *= 0.125f;
            if (maskt) {
                const int c0 = k0 + nf * 8 + t4 * 2, c1 = c0 + 1;
                if (c0 > r0g) s[nf][0] = -1e9f;
                if (c1 > r0g) s[nf][1] = -1e9f;
                if (c0 > r1g) s[nf][2] = -1e9f;
                if (c1 > r1g) s[nf][3] = -1e9f;
            }
        }

        float mx0 = -CUDART_INF_F, mx1 = -CUDART_INF_F;
#pragma unroll
        for (int nf = 0; nf < 8; nf++) {
            mx0 = fmaxf(mx0, fmaxf(s[nf][0], s[nf][1]));
            mx1 = fmaxf(mx1, fmaxf(s[nf][2], s[nf][3]));
        }
        mx0 = fmaxf(mx0, __shfl_xor_sync(0xffffffffu, mx0, 1));
        mx0 = fmaxf(mx0, __shfl_xor_sync(0xffffffffu, mx0, 2));
        mx1 = fmaxf(mx1, __shfl_xor_sync(0xffffffffu, mx1, 1));
        mx1 = fmaxf(mx1, __shfl_xor_sync(0xffffffffu, mx1, 2));
        const float mn0 = fmaxf(mr0, mx0), mn1 = fmaxf(mr1, mx1);
        const float cr0 = __expf(mr0 - mn0), cr1 = __expf(mr1 - mn1);
        float sum0 = 0.f, sum1 = 0.f;
#pragma unroll
        for (int nf = 0; nf < 8; nf++) {
            s[nf][0] = __expf(s[nf][0] - mn0); sum0 += s[nf][0];
            s[nf][1] = __expf(s[nf][1] - mn0); sum0 += s[nf][1];
            s[nf][2] = __expf(s[nf][2] - mn1); sum1 += s[nf][2];
            s[nf][3] = __expf(s[nf][3] - mn1); sum1 += s[nf][3];
        }
        sum0 += __shfl_xor_sync(0xffffffffu, sum0, 1);
        sum0 += __shfl_xor_sync(0xffffffffu, sum0, 2);
        sum1 += __shfl_xor_sync(0xffffffffu, sum1, 1);
        sum1 += __shfl_xor_sync(0xffffffffu, sum1, 2);
        lr0 = lr0 * cr0 + sum0;
        lr1 = lr1 * cr1 + sum1;
        mr0 = mn0; mr1 = mn1;
#pragma unroll
        for (int nf = 0; nf < 8; nf++) {
            out[nf][0] *= cr0; out[nf][1] *= cr0;
            out[nf][2] *= cr1; out[nf][3] *= cr1;
        }

        const int vrow = (lane & 7) + ((lane >> 4) << 3);
        const int vcol = (lane & 8);
#pragma unroll
        for (int ks = 0; ks < 4; ks++) {
            uint32_t ph[4], pl[4];
            {
                float l0, l1;
                ph[0] = pack_hi(s[2*ks][0],   s[2*ks][1],   l0, l1); pl[0] = pack2(l0, l1);
                ph[1] = pack_hi(s[2*ks][2],   s[2*ks][3],   l0, l1); pl[1] = pack2(l0, l1);
                ph[2] = pack_hi(s[2*ks+1][0], s[2*ks+1][1], l0, l1); pl[2] = pack2(l0, l1);
                ph[3] = pack_hi(s[2*ks+1][2], s[2*ks+1][3], l0, l1); pl[3] = pack2(l0, l1);
            }
#pragma unroll
            for (int nb = 0; nb < 4; nb++) {
                uint32_t vh[4], vl[4];
                const uint32_t a = kb + 2 * F_TILE + (ks * 16 + vrow) * 144 +
                                   (nb * 16 + vcol) * 2;
                ldsm4t(vh, a);
                ldsm4t(vl, a + F_TILE);
                mma_bf16(out[2*nb],   ph, vh[0], vh[2]);
                mma_bf16(out[2*nb],   ph, vl[0], vl[2]);
                mma_bf16(out[2*nb],   pl, vh[0], vh[2]);
                mma_bf16(out[2*nb+1], ph, vh[1], vh[3]);
                mma_bf16(out[2*nb+1], ph, vl[1], vl[3]);
                mma_bf16(out[2*nb+1], pl, vh[1], vh[3]);
            }
        }
        __syncthreads();
    }

    const float inv0 = 1.f / lr0, inv1 = 1.f / lr1;
    const size_t bs0 = (size_t)(bb * SEQ + qbase + wq + grp) * DMODEL;
    const size_t bs1 = bs0 + 8 * DMODEL;
#pragma unroll
    for (int nf = 0; nf < 8; nf++) {
        const int col = hd * 64 + nf * 8 + t4 * 2;
        float l0, l1;
        uint32_t hp = pack_hi(out[nf][0] * inv0, out[nf][1] * inv0, l0, l1);
        *(uint32_t*)&g_Ohi[bs0 + col] = hp;
        *(uint32_t*)&g_Olo[bs0 + col] = pack2(l0, l1);
        hp = pack_hi(out[nf][2] * inv1, out[nf][3] * inv1, l0, l1);
        *(uint32_t*)&g_Ohi[bs1 + col] = hp;
        *(uint32_t*)&g_Olo[bs1 + col] = pack2(l0, l1);
    }
}

// ============================================================================
extern "C" void kernel_launch(void* const* d_in, const int* in_sizes, int n_in,
                              void* d_out, int out_size)
{
    (void)in_sizes; (void)n_in; (void)out_size;
    const float* q  = (const float*)d_in[0];
    const float* k  = (const float*)d_in[1];
    const float* v  = (const float*)d_in[2];
    const float* Wq = (const float*)d_in[4];
    const float* bq = (const float*)d_in[5];
    const float* Wk = (const float*)d_in[6];
    const float* bk = (const float*)d_in[7];
    const float* Wv = (const float*)d_in[8];
    const float* bv = (const float*)d_in[9];
    const float* Wo = (const float*)d_in[10];
    const float* bo = (const float*)d_in[11];
    float* out = (float*)d_out;

    cudaFuncSetAttribute(gemm_bf16x3<0>, cudaFuncAttributeMaxDynamicSharedMemorySize, GEMM_SMEM);
    cudaFuncSetAttribute(gemm_bf16x3<1>, cudaFuncAttributeMaxDynamicSharedMemorySize, GEMM_SMEM);
    cudaFuncSetAttribute(flash_hmma, cudaFuncAttributeMaxDynamicSharedMemorySize, FLASH_SMEM);

    const dim3 tb(256);
    split_x<<<dim3(NELX/4/256, 3), tb>>>(q, k, v);
    split_w<<<dim3(NELW/4/256, 4), tb>>>(Wq, Wk, Wv, Wo);

    GB g0; g0.b[0] = bq; g0.b[1] = bk; g0.b[2] = bv; g0.out = nullptr;
    gemm_bf16x3<0><<<dim3(DMODEL/128, MTOT/128, 3), tb, GEMM_SMEM>>>(g0);

    flash_hmma<<<dim3(SEQ/128, BATCH*NHEAD), tb, FLASH_SMEM>>>();

    GB g1; g1.b[0] = bo; g1.b[1] = nullptr; g1.b[2] = nullptr; g1.out = out;
    gemm_bf16x3<1><<<dim3(DMODEL/128, MTOT/128, 1), tb, GEMM_SMEM>>>(g1);
}